// round 6
// baseline (speedup 1.0000x reference)
#include <cuda_runtime.h>
#include <cstdint>

typedef unsigned int u32;

#define Nq 8192
#define Mq 8192
#define Dq 64
#define TNr 128
#define NCHUNK 64
#define THREADS 512

#define SR 68    // row stride (floats): 68 % 32 == 4 -> conflict-free frag patterns

#define C1F (1.0f/(128.0f*0.69314718055994531f))
#define C2F (2.0f*C1F)

// SMEM float offsets
#define OFF_P   0
#define OFF_R   (OFF_P + 128*SR)            // 2 buffers
#define OFF_NUM (OFF_R + 2*128*SR)          // 2 buffers x 128*SR
#define OFF_SQP (OFF_NUM + 2*128*SR)
#define OFF_SQR (OFF_SQP + 128)             // 2 x 128
#define OFF_DEN (OFF_SQR + 256)             // 4 x 128
#define SMEM_F  (OFF_DEN + 512)

__device__ __forceinline__ void mma_tf32(float c[4], u32 a0, u32 a1, u32 a2, u32 a3,
                                         u32 b0, u32 b1)
{
    asm volatile(
        "mma.sync.aligned.m16n8k8.row.col.f32.tf32.tf32.f32 "
        "{%0,%1,%2,%3}, {%4,%5,%6,%7}, {%8,%9}, {%0,%1,%2,%3};"
        : "+f"(c[0]), "+f"(c[1]), "+f"(c[2]), "+f"(c[3])
        : "r"(a0), "r"(a1), "r"(a2), "r"(a3), "r"(b0), "r"(b1));
}
__device__ __forceinline__ float ex2(float x){
    float r; asm("ex2.approx.ftz.f32 %0, %1;" : "=f"(r) : "f"(x)); return r;
}
__device__ __forceinline__ float rcpf(float x){
    float r; asm("rcp.approx.ftz.f32 %0, %1;" : "=f"(r) : "f"(x)); return r;
}
// Round fp32 -> tf32 (round-to-nearest), fp32 container
__device__ __forceinline__ float rtf(float x){
    u32 r; asm("cvt.rna.tf32.f32 %0, %1;" : "=r"(r) : "f"(x));
    return __uint_as_float(r);
}
__device__ __forceinline__ void cpasync16(u32 dst, const void* src){
    asm volatile("cp.async.cg.shared.global [%0], [%1], 16;" :: "r"(dst), "l"(src));
}
__device__ __forceinline__ u32 fbits(float x){ return __float_as_uint(x); }

__global__ void __launch_bounds__(THREADS, 1) ms_kernel(
    const float* __restrict__ P, const float* __restrict__ Rf, float* __restrict__ out)
{
    extern __shared__ float sm[];
    float* Ps   = sm + OFF_P;
    float* Rs0  = sm + OFF_R;
    float* numb = sm + OFF_NUM;
    float* sqp  = sm + OFF_SQP;
    float* sqr0 = sm + OFF_SQR;
    float* denp = sm + OFF_DEN;

    const int t = threadIdx.x;
    const int w = t >> 5, l = t & 31;
    const int gid = l >> 2, tig = l & 3;       // groupID, threadID-in-group
    const int b = blockIdx.y;
    const int n0 = blockIdx.x * TNr;
    const float* Pb = P + ((size_t)b * Nq + n0) * Dq;
    const float* Rb = Rf + (size_t)b * Mq * Dq;

    // Warp grid 4m x 4quarter: wm rows; wn = GEMM1 n-slice = GEMM2 private k-slice
    const int wm = (w & 3) * 32;
    const int qt = w >> 2;                     // 0..3
    const int wn = qt * 32;

    // ---- Prologue: cp.async R chunk 0; direct-load P (tf32-rounded) + row norms ----
    {
        const float4* g4 = (const float4*)Rb;
        #pragma unroll
        for (int it = 0; it < 4; it++){
            int idx = t + (it << 9);
            int r = idx >> 4, c4 = idx & 15;
            u32 dst = (u32)__cvta_generic_to_shared(&Rs0[r * SR + c4 * 4]);
            cpasync16(dst, g4 + idx);
        }
        asm volatile("cp.async.commit_group;");
    }
    {
        const float4* g4 = (const float4*)Pb;
        #pragma unroll
        for (int it = 0; it < 4; it++){
            int idx = t + (it << 9);
            int r = idx >> 4, c4 = idx & 15;
            float4 v = g4[idx];
            v.x = rtf(v.x); v.y = rtf(v.y); v.z = rtf(v.z); v.w = rtf(v.w);
            *(float4*)&Ps[r * SR + c4 * 4] = v;
            float s = v.x*v.x + v.y*v.y + v.z*v.z + v.w*v.w;
            s += __shfl_xor_sync(0xffffffffu, s, 1);
            s += __shfl_xor_sync(0xffffffffu, s, 2);
            s += __shfl_xor_sync(0xffffffffu, s, 4);
            s += __shfl_xor_sync(0xffffffffu, s, 8);
            if ((l & 15) == 0) sqp[r] = s * C1F;
        }
    }

    // Partial numerator over this warp's k-quarter: 32m x 64n
    float nacc[2][8][4];
    float dacc[4];
    #pragma unroll
    for (int i = 0; i < 2; i++)
        #pragma unroll
        for (int j = 0; j < 8; j++)
            #pragma unroll
            for (int q = 0; q < 4; q++) nacc[i][j][q] = 0.f;
    #pragma unroll
    for (int i = 0; i < 4; i++) dacc[i] = 0.f;

    for (int i = 0; i < NCHUNK; i++){
        const int p = i & 1;
        float* Rs  = Rs0 + p * 128 * SR;
        float* sqr = sqr0 + p * 128;

        asm volatile("cp.async.wait_group 0;" ::: "memory");
        __syncthreads();

        if (i + 1 < NCHUNK){
            float* Rn = Rs0 + (p ^ 1) * 128 * SR;
            const float4* g4 = (const float4*)(Rb + (size_t)(i + 1) * 128 * Dq);
            #pragma unroll
            for (int it = 0; it < 4; it++){
                int idx = t + (it << 9);
                int r = idx >> 4, c4 = idx & 15;
                u32 dst = (u32)__cvta_generic_to_shared(&Rn[r * SR + c4 * 4]);
                cpasync16(dst, g4 + idx);
            }
            asm volatile("cp.async.commit_group;");
        }

        // R pass: round to tf32 in place + row norms (from rounded values)
        {
            int r = t >> 2, h = t & 3;
            float4* row = (float4*)&Rs[r * SR + h * 16];
            float s = 0.f;
            #pragma unroll
            for (int j = 0; j < 4; j++){
                float4 v = row[j];
                v.x = rtf(v.x); v.y = rtf(v.y); v.z = rtf(v.z); v.w = rtf(v.w);
                row[j] = v;
                s += v.x*v.x + v.y*v.y + v.z*v.z + v.w*v.w;
            }
            s += __shfl_xor_sync(0xffffffffu, s, 1);
            s += __shfl_xor_sync(0xffffffffu, s, 2);
            if (h == 0) sqr[r] = s * C1F;
        }
        __syncthreads();

        // ---- GEMM1: S = P . R^T  (warp tile 32 x 32) ----
        float sa[2][4][4];
        #pragma unroll
        for (int mt = 0; mt < 2; mt++)
            #pragma unroll
            for (int nt = 0; nt < 4; nt++)
                #pragma unroll
                for (int q = 0; q < 4; q++) sa[mt][nt][q] = 0.f;

        #pragma unroll
        for (int ks = 0; ks < 8; ks++){
            u32 a[2][4];
            #pragma unroll
            for (int mt = 0; mt < 2; mt++){
                const float* pa = &Ps[(wm + 16*mt + gid) * SR + ks*8 + tig];
                a[mt][0] = fbits(pa[0]);
                a[mt][1] = fbits(pa[8*SR]);
                a[mt][2] = fbits(pa[4]);
                a[mt][3] = fbits(pa[8*SR + 4]);
            }
            #pragma unroll
            for (int nt = 0; nt < 4; nt++){
                const float* pb = &Rs[(wn + 8*nt + gid) * SR + ks*8 + tig];
                u32 b0 = fbits(pb[0]), b1 = fbits(pb[4]);
                #pragma unroll
                for (int mt = 0; mt < 2; mt++)
                    mma_tf32(sa[mt][nt], a[mt][0], a[mt][1], a[mt][2], a[mt][3], b0, b1);
            }
        }

        // ---- Epilogue in registers: sa <- rtf(exp2(C2*S - |p|^2 - |r|^2)); den partials ----
        #pragma unroll
        for (int mt = 0; mt < 2; mt++){
            int r0 = wm + 16*mt + gid;
            float spa0 = sqp[r0];
            float spa1 = sqp[r0 + 8];
            #pragma unroll
            for (int nt = 0; nt < 4; nt++){
                int c0 = wn + 8*nt + 2*tig;
                float2 q = *(const float2*)&sqr[c0];
                float e0 = rtf(ex2(fmaf(C2F, sa[mt][nt][0], -spa0 - q.x)));
                float e1 = rtf(ex2(fmaf(C2F, sa[mt][nt][1], -spa0 - q.y)));
                float e2 = rtf(ex2(fmaf(C2F, sa[mt][nt][2], -spa1 - q.x)));
                float e3 = rtf(ex2(fmaf(C2F, sa[mt][nt][3], -spa1 - q.y)));
                dacc[2*mt + 0] += e0 + e1;
                dacc[2*mt + 1] += e2 + e3;
                sa[mt][nt][0] = e0; sa[mt][nt][1] = e1;
                sa[mt][nt][2] = e2; sa[mt][nt][3] = e3;
            }
        }

        // ---- GEMM2: num_partial += K_regs . R  (k = this warp's 32 rows) ----
        // k-permutation sigma(j)=2j / 2(j-4)+1: (a0,a1,a2,a3) = (c0,c2,c1,c3),
        // B rows permuted to match.
        #pragma unroll
        for (int kt = 0; kt < 4; kt++){
            u32 a0[2], a1[2], a2[2], a3[2];
            #pragma unroll
            for (int mt = 0; mt < 2; mt++){
                a0[mt] = fbits(sa[mt][kt][0]);
                a1[mt] = fbits(sa[mt][kt][2]);
                a2[mt] = fbits(sa[mt][kt][1]);
                a3[mt] = fbits(sa[mt][kt][3]);
            }
            const float* pb = &Rs[(wn + 8*kt + 2*tig) * SR + gid];
            #pragma unroll
            for (int jt = 0; jt < 8; jt++){
                u32 b0 = fbits(pb[8*jt]);
                u32 b1 = fbits(pb[SR + 8*jt]);
                #pragma unroll
                for (int mt = 0; mt < 2; mt++)
                    mma_tf32(nacc[mt][jt], a0[mt], a1[mt], a2[mt], a3[mt], b0, b1);
            }
        }
    }

    // ---- Denominator: reduce over col-lanes, publish per-quarter partials ----
    #pragma unroll
    for (int d = 0; d < 4; d++){
        dacc[d] += __shfl_xor_sync(0xffffffffu, dacc[d], 1);
        dacc[d] += __shfl_xor_sync(0xffffffffu, dacc[d], 2);
    }
    if (tig == 0){
        #pragma unroll
        for (int mt = 0; mt < 2; mt++){
            denp[qt * 128 + wm + 16*mt + gid]     = dacc[2*mt + 0];
            denp[qt * 128 + wm + 16*mt + 8 + gid] = dacc[2*mt + 1];
        }
    }

    // ---- Combine the four k-quarter numerator partials: 2 buffers + add pass ----
    __syncthreads();
    float* nb = numb + (qt & 1) * 128 * SR;
    if (qt < 2){
        #pragma unroll
        for (int mt = 0; mt < 2; mt++){
            int r0 = wm + 16*mt + gid;
            #pragma unroll
            for (int jt = 0; jt < 8; jt++){
                int c0 = 8*jt + 2*tig;
                *(float2*)&nb[r0 * SR + c0]       = make_float2(nacc[mt][jt][0], nacc[mt][jt][1]);
                *(float2*)&nb[(r0 + 8) * SR + c0] = make_float2(nacc[mt][jt][2], nacc[mt][jt][3]);
            }
        }
    }
    __syncthreads();
    if (qt >= 2){
        #pragma unroll
        for (int mt = 0; mt < 2; mt++){
            int r0 = wm + 16*mt + gid;
            #pragma unroll
            for (int jt = 0; jt < 8; jt++){
                int c0 = 8*jt + 2*tig;
                float2 u0 = *(const float2*)&nb[r0 * SR + c0];
                float2 u1 = *(const float2*)&nb[(r0 + 8) * SR + c0];
                u0.x += nacc[mt][jt][0]; u0.y += nacc[mt][jt][1];
                u1.x += nacc[mt][jt][2]; u1.y += nacc[mt][jt][3];
                *(float2*)&nb[r0 * SR + c0]       = u0;
                *(float2*)&nb[(r0 + 8) * SR + c0] = u1;
            }
        }
    }
    __syncthreads();

    // ---- Coalesced writeback: out = (num0 + num1) / den ----
    float4* Ob = (float4*)(out + ((size_t)b * Nq + n0) * Dq);
    #pragma unroll
    for (int it = 0; it < 4; it++){
        int idx = t + (it << 9);
        int r = idx >> 4, c4 = idx & 15;
        float4 v0 = *(const float4*)&numb[r * SR + c4 * 4];
        float4 v1 = *(const float4*)&numb[128 * SR + r * SR + c4 * 4];
        float den = denp[r] + denp[128 + r] + denp[256 + r] + denp[384 + r];
        float inv = rcpf(den);
        float4 v;
        v.x = (v0.x + v1.x) * inv;
        v.y = (v0.y + v1.y) * inv;
        v.z = (v0.z + v1.z) * inv;
        v.w = (v0.w + v1.w) * inv;
        Ob[idx] = v;
    }
}

extern "C" void kernel_launch(void* const* d_in, const int* in_sizes, int n_in,
                              void* d_out, int out_size)
{
    const float* points = (const float*)d_in[0];
    const float* refp   = (const float*)d_in[1];
    float* out          = (float*)d_out;

    const int smem_bytes = SMEM_F * (int)sizeof(float);
    static int attr_set = 0;
    if (!attr_set){
        cudaFuncSetAttribute(ms_kernel,
                             cudaFuncAttributeMaxDynamicSharedMemorySize, smem_bytes);
        attr_set = 1;
    }
    dim3 grid(Nq / TNr, 2);
    ms_kernel<<<grid, THREADS, smem_bytes>>>(points, refp, out);
}

// round 9
// speedup vs baseline: 1.2736x; 1.2736x over previous
#include <cuda_runtime.h>
#include <cstdint>

typedef unsigned int u32;

#define Nq 8192
#define Mq 8192
#define Dq 64
#define TNr 128
#define NCHUNK 64

#define SR 68    // row stride (floats): 68 % 32 == 4 -> conflict-free frag patterns

#define C1F (1.0f/(128.0f*0.69314718055994531f))
#define C2F (2.0f*C1F)

// SMEM float offsets
#define OFF_P   0
#define OFF_R   (OFF_P + 128*SR)            // 2 buffers
#define OFF_NUM (OFF_R + 2*128*SR)          // 128 x SR num staging
#define OFF_SQP (OFF_NUM + 128*SR)
#define OFF_SQR (OFF_SQP + 128)             // 2 x 128
#define OFF_DEN (OFF_SQR + 256)             // 2 x 128
#define SMEM_F  (OFF_DEN + 256)

// Pre-rounded (tf32) copies + norms, produced by prep_kernel
__device__ float g_Pr[2 * Nq * Dq];
__device__ float g_Rr[2 * Mq * Dq];
__device__ float g_sqp[2 * Nq];
__device__ float g_sqr[2 * Mq];

__device__ __forceinline__ void mma_tf32(float c[4], u32 a0, u32 a1, u32 a2, u32 a3,
                                         u32 b0, u32 b1)
{
    asm volatile(
        "mma.sync.aligned.m16n8k8.row.col.f32.tf32.tf32.f32 "
        "{%0,%1,%2,%3}, {%4,%5,%6,%7}, {%8,%9}, {%0,%1,%2,%3};"
        : "+f"(c[0]), "+f"(c[1]), "+f"(c[2]), "+f"(c[3])
        : "r"(a0), "r"(a1), "r"(a2), "r"(a3), "r"(b0), "r"(b1));
}
__device__ __forceinline__ float ex2(float x){
    float r; asm("ex2.approx.ftz.f32 %0, %1;" : "=f"(r) : "f"(x)); return r;
}
__device__ __forceinline__ float rcpf(float x){
    float r; asm("rcp.approx.ftz.f32 %0, %1;" : "=f"(r) : "f"(x)); return r;
}
// Round fp32 -> tf32 (round-to-nearest), fp32 container
__device__ __forceinline__ float rtf(float x){
    u32 r; asm("cvt.rna.tf32.f32 %0, %1;" : "=r"(r) : "f"(x));
    return __uint_as_float(r);
}
__device__ __forceinline__ void cpasync16(u32 dst, const void* src){
    asm volatile("cp.async.cg.shared.global [%0], [%1], 16;" :: "r"(dst), "l"(src));
}
__device__ __forceinline__ u32 fbits(float x){ return __float_as_uint(x); }

// One warp per row: write tf32-rounded row + C1*|row~|^2
__global__ void prep_kernel(const float* __restrict__ P, const float* __restrict__ R)
{
    int warp = (blockIdx.x * blockDim.x + threadIdx.x) >> 5;
    int lane = threadIdx.x & 31;
    const float* src; float* dst; float* nrm;
    if (warp < 2 * Nq){
        src = P + (size_t)warp * Dq; dst = g_Pr + (size_t)warp * Dq; nrm = g_sqp + warp;
    } else {
        int row = warp - 2 * Nq;
        src = R + (size_t)row * Dq; dst = g_Rr + (size_t)row * Dq; nrm = g_sqr + row;
    }
    float2 v = ((const float2*)src)[lane];
    v.x = rtf(v.x); v.y = rtf(v.y);
    ((float2*)dst)[lane] = v;
    float s = v.x * v.x + v.y * v.y;
    #pragma unroll
    for (int o = 16; o; o >>= 1) s += __shfl_xor_sync(0xffffffffu, s, o);
    if (lane == 0) nrm[0] = s * C1F;
}

__global__ void __launch_bounds__(256, 1) ms_kernel(float* __restrict__ out)
{
    extern __shared__ float sm[];
    float* Ps   = sm + OFF_P;
    float* Rs0  = sm + OFF_R;
    float* numb = sm + OFF_NUM;
    float* sqp  = sm + OFF_SQP;
    float* sqr0 = sm + OFF_SQR;
    float* denp = sm + OFF_DEN;

    const int t = threadIdx.x;
    const int w = t >> 5, l = t & 31;
    const int gid = l >> 2, tig = l & 3;       // groupID, threadID-in-group
    const int b = blockIdx.y;
    const int n0 = blockIdx.x * TNr;
    const float* Pb = g_Pr + ((size_t)b * Nq + n0) * Dq;
    const float* Rb = g_Rr + (size_t)b * Mq * Dq;
    const float* sqpg = g_sqp + b * Nq + n0;
    const float* sqrg = g_sqr + b * Mq;

    // Warp grid 4m x 2half: wm rows, half = GEMM1 n-slice = GEMM2 private k-half
    const int wm = (w & 3) * 32;
    const int half = w >> 2;
    const int wn1 = half * 64;

    // ---- Prologue: cp.async P tile + sqp + R chunk 0 + sqr0 (one group) ----
    {
        const float4* g4 = (const float4*)Pb;
        #pragma unroll
        for (int it = 0; it < 8; it++){
            int idx = t + (it << 8);
            int r = idx >> 4, c4 = idx & 15;
            cpasync16((u32)__cvta_generic_to_shared(&Ps[r * SR + c4 * 4]), g4 + idx);
        }
        const float4* r4 = (const float4*)Rb;
        #pragma unroll
        for (int it = 0; it < 8; it++){
            int idx = t + (it << 8);
            int r = idx >> 4, c4 = idx & 15;
            cpasync16((u32)__cvta_generic_to_shared(&Rs0[r * SR + c4 * 4]), r4 + idx);
        }
        if (t < 32) cpasync16((u32)__cvta_generic_to_shared(&sqp[t * 4]), sqpg + t * 4);
        if (t >= 32 && t < 64)
            cpasync16((u32)__cvta_generic_to_shared(&sqr0[(t - 32) * 4]), sqrg + (t - 32) * 4);
        asm volatile("cp.async.commit_group;");
    }

    // Partial numerator over this warp's k-half: 32m x 64n ; den via ones-MMA
    float nacc[2][8][4];
    float denacc[2][4];
    #pragma unroll
    for (int i = 0; i < 2; i++){
        #pragma unroll
        for (int j = 0; j < 8; j++)
            #pragma unroll
            for (int q = 0; q < 4; q++) nacc[i][j][q] = 0.f;
        #pragma unroll
        for (int q = 0; q < 4; q++) denacc[i][q] = 0.f;
    }
    const u32 ONE = 0x3f800000u;

    for (int i = 0; i < NCHUNK; i++){
        const int p = i & 1;
        float* Rs  = Rs0 + p * 128 * SR;
        float* sqr = sqr0 + p * 128;

        asm volatile("cp.async.wait_group 0;" ::: "memory");
        __syncthreads();   // data ready for all; also fences old-buffer readers before prefetch

        if (i + 1 < NCHUNK){
            float* Rn = Rs0 + (p ^ 1) * 128 * SR;
            const float4* g4 = (const float4*)(Rb + (size_t)(i + 1) * 128 * Dq);
            #pragma unroll
            for (int it = 0; it < 8; it++){
                int idx = t + (it << 8);
                int r = idx >> 4, c4 = idx & 15;
                cpasync16((u32)__cvta_generic_to_shared(&Rn[r * SR + c4 * 4]), g4 + idx);
            }
            if (t < 32)
                cpasync16((u32)__cvta_generic_to_shared(&sqr0[(p ^ 1) * 128 + t * 4]),
                          sqrg + (size_t)(i + 1) * 128 + t * 4);
            asm volatile("cp.async.commit_group;");
        }

        // ---- GEMM1: S = P . R^T  (warp tile 32 x 64) ----
        float sa[2][8][4];
        #pragma unroll
        for (int mt = 0; mt < 2; mt++)
            #pragma unroll
            for (int nt = 0; nt < 8; nt++)
                #pragma unroll
                for (int q = 0; q < 4; q++) sa[mt][nt][q] = 0.f;

        #pragma unroll
        for (int ks = 0; ks < 8; ks++){
            u32 a[2][4];
            #pragma unroll
            for (int mt = 0; mt < 2; mt++){
                const float* pa = &Ps[(wm + 16*mt + gid) * SR + ks*8 + tig];
                a[mt][0] = fbits(pa[0]);
                a[mt][1] = fbits(pa[8*SR]);
                a[mt][2] = fbits(pa[4]);
                a[mt][3] = fbits(pa[8*SR + 4]);
            }
            #pragma unroll
            for (int nt = 0; nt < 8; nt++){
                const float* pb = &Rs[(wn1 + 8*nt + gid) * SR + ks*8 + tig];
                u32 b0 = fbits(pb[0]), b1 = fbits(pb[4]);
                #pragma unroll
                for (int mt = 0; mt < 2; mt++)
                    mma_tf32(sa[mt][nt], a[mt][0], a[mt][1], a[mt][2], a[mt][3], b0, b1);
            }
        }

        // ---- Epilogue in registers: sa <- exp2(C2*S - |p|^2 - |r|^2)  (no rounding) ----
        #pragma unroll
        for (int mt = 0; mt < 2; mt++){
            int r0 = wm + 16*mt + gid;
            float spa0 = sqp[r0];
            float spa1 = sqp[r0 + 8];
            #pragma unroll
            for (int nt = 0; nt < 8; nt++){
                int c0 = wn1 + 8*nt + 2*tig;
                float2 q = *(const float2*)&sqr[c0];
                sa[mt][nt][0] = ex2(fmaf(C2F, sa[mt][nt][0], -spa0 - q.x));
                sa[mt][nt][1] = ex2(fmaf(C2F, sa[mt][nt][1], -spa0 - q.y));
                sa[mt][nt][2] = ex2(fmaf(C2F, sa[mt][nt][2], -spa1 - q.x));
                sa[mt][nt][3] = ex2(fmaf(C2F, sa[mt][nt][3], -spa1 - q.y));
            }
        }

        // ---- GEMM2: num_partial += K_regs . R ; den_partial += K_regs . ones ----
        // k-permutation sigma(j)=2j / 2(j-4)+1: (a0,a1,a2,a3) = (c0,c2,c1,c3),
        // B rows permuted to match. den uses the SAME truncated A -> bias cancels.
        #pragma unroll
        for (int kt = 0; kt < 8; kt++){
            u32 a0[2], a1[2], a2[2], a3[2];
            #pragma unroll
            for (int mt = 0; mt < 2; mt++){
                a0[mt] = fbits(sa[mt][kt][0]);
                a1[mt] = fbits(sa[mt][kt][2]);
                a2[mt] = fbits(sa[mt][kt][1]);
                a3[mt] = fbits(sa[mt][kt][3]);
            }
            const float* pb = &Rs[(wn1 + 8*kt + 2*tig) * SR + gid];
            #pragma unroll
            for (int jt = 0; jt < 8; jt++){
                u32 b0 = fbits(pb[8*jt]);
                u32 b1 = fbits(pb[SR + 8*jt]);
                #pragma unroll
                for (int mt = 0; mt < 2; mt++)
                    mma_tf32(nacc[mt][jt], a0[mt], a1[mt], a2[mt], a3[mt], b0, b1);
            }
            #pragma unroll
            for (int mt = 0; mt < 2; mt++)
                mma_tf32(denacc[mt], a0[mt], a1[mt], a2[mt], a3[mt], ONE, ONE);
        }
    }

    // ---- Denominator: cols of ones-MMA are identical; publish per-half partials ----
    if (tig == 0){
        #pragma unroll
        for (int mt = 0; mt < 2; mt++){
            denp[half * 128 + wm + 16*mt + gid]     = denacc[mt][0];
            denp[half * 128 + wm + 16*mt + 8 + gid] = denacc[mt][2];
        }
    }

    // ---- Combine the two k-half numerator partials in SMEM ----
    __syncthreads();
    if (half == 0){
        #pragma unroll
        for (int mt = 0; mt < 2; mt++){
            int r0 = wm + 16*mt + gid;
            #pragma unroll
            for (int jt = 0; jt < 8; jt++){
                int c0 = 8*jt + 2*tig;
                *(float2*)&numb[r0 * SR + c0]       = make_float2(nacc[mt][jt][0], nacc[mt][jt][1]);
                *(float2*)&numb[(r0 + 8) * SR + c0] = make_float2(nacc[mt][jt][2], nacc[mt][jt][3]);
            }
        }
    }
    __syncthreads();
    if (half == 1){
        #pragma unroll
        for (int mt = 0; mt < 2; mt++){
            int r0 = wm + 16*mt + gid;
            #pragma unroll
            for (int jt = 0; jt < 8; jt++){
                int c0 = 8*jt + 2*tig;
                float2 u0 = *(const float2*)&numb[r0 * SR + c0];
                float2 u1 = *(const float2*)&numb[(r0 + 8) * SR + c0];
                u0.x += nacc[mt][jt][0]; u0.y += nacc[mt][jt][1];
                u1.x += nacc[mt][jt][2]; u1.y += nacc[mt][jt][3];
                *(float2*)&numb[r0 * SR + c0]       = u0;
                *(float2*)&numb[(r0 + 8) * SR + c0] = u1;
            }
        }
    }
    __syncthreads();

    // ---- Coalesced writeback: out = num / den ----
    float4* Ob = (float4*)(out + ((size_t)b * Nq + n0) * Dq);
    #pragma unroll
    for (int it = 0; it < 8; it++){
        int idx = t + (it << 8);
        int r = idx >> 4, c4 = idx & 15;
        float4 v = *(const float4*)&numb[r * SR + c4 * 4];
        float inv = rcpf(denp[r] + denp[128 + r]);
        v.x *= inv; v.y *= inv; v.z *= inv; v.w *= inv;
        Ob[idx] = v;
    }
}

extern "C" void kernel_launch(void* const* d_in, const int* in_sizes, int n_in,
                              void* d_out, int out_size)
{
    const float* points = (const float*)d_in[0];
    const float* refp   = (const float*)d_in[1];
    float* out          = (float*)d_out;

    // Prep: 2*Nq + 2*Mq rows, one warp each, 8 warps/block
    {
        int warps = 2 * Nq + 2 * Mq;
        prep_kernel<<<warps / 8, 256>>>(points, refp);
    }

    const int smem_bytes = SMEM_F * (int)sizeof(float);
    static int attr_set = 0;
    if (!attr_set){
        cudaFuncSetAttribute(ms_kernel,
                             cudaFuncAttributeMaxDynamicSharedMemorySize, smem_bytes);
        attr_set = 1;
    }
    dim3 grid(Nq / TNr, 2);
    ms_kernel<<<grid, 256, smem_bytes>>>(out);
}

// round 11
// speedup vs baseline: 1.4228x; 1.1172x over previous
#include <cuda_runtime.h>
#include <cuda_fp16.h>
#include <cstdint>

typedef unsigned int u32;

#define Nq 8192
#define Mq 8192
#define Dq 64
#define TNr 128
#define NCHUNK 64

#define SR 68    // fp32 row stride (floats): 68 % 32 == 4 -> conflict-free frag patterns

#define C1F (1.0f/(128.0f*0.69314718055994531f))
#define C2F (2.0f*C1F)

// SMEM float/word offsets
#define OFF_P    0
#define OFF_R    (OFF_P + 128*SR)           // 2 buffers
#define OFF_NUM  (OFF_R + 2*128*SR)         // 128 x SR num staging
#define OFF_SQP  (OFF_NUM + 128*SR)
#define OFF_SQR  (OFF_SQP + 128)            // 2 x 128
#define OFF_DEN  (OFF_SQR + 256)            // 2 x 128
#define OFF_RT   (OFF_DEN + 256)            // 2 buffers x 64 rows x 68 u32 (fp16 R^T)
#define SMEM_F   (OFF_RT + 2*64*68)

// Pre-rounded (tf32) copies + norms + transposed fp16 R
__device__ float g_Pr[2 * Nq * Dq];
__device__ float g_Rr[2 * Mq * Dq];
__device__ float g_sqp[2 * Nq];
__device__ float g_sqr[2 * Mq];
__device__ u32   g_Rt[2 * 64 * 4096];       // per chunk: 64 d-rows x 128 kk (fp16) = 4096 u32

__device__ __forceinline__ void mma_tf32(float c[4], u32 a0, u32 a1, u32 a2, u32 a3,
                                         u32 b0, u32 b1)
{
    asm volatile(
        "mma.sync.aligned.m16n8k8.row.col.f32.tf32.tf32.f32 "
        "{%0,%1,%2,%3}, {%4,%5,%6,%7}, {%8,%9}, {%0,%1,%2,%3};"
        : "+f"(c[0]), "+f"(c[1]), "+f"(c[2]), "+f"(c[3])
        : "r"(a0), "r"(a1), "r"(a2), "r"(a3), "r"(b0), "r"(b1));
}
__device__ __forceinline__ void mma_f16(float c[4], u32 a0, u32 a1, u32 a2, u32 a3,
                                        u32 b0, u32 b1)
{
    asm volatile(
        "mma.sync.aligned.m16n8k16.row.col.f32.f16.f16.f32 "
        "{%0,%1,%2,%3}, {%4,%5,%6,%7}, {%8,%9}, {%0,%1,%2,%3};"
        : "+f"(c[0]), "+f"(c[1]), "+f"(c[2]), "+f"(c[3])
        : "r"(a0), "r"(a1), "r"(a2), "r"(a3), "r"(b0), "r"(b1));
}
__device__ __forceinline__ float ex2(float x){
    float r; asm("ex2.approx.ftz.f32 %0, %1;" : "=f"(r) : "f"(x)); return r;
}
__device__ __forceinline__ float rcpf(float x){
    float r; asm("rcp.approx.ftz.f32 %0, %1;" : "=f"(r) : "f"(x)); return r;
}
__device__ __forceinline__ float rtf(float x){
    u32 r; asm("cvt.rna.tf32.f32 %0, %1;" : "=r"(r) : "f"(x));
    return __uint_as_float(r);
}
// pack two fp32 -> f16x2 (first k element in low half, second in high half)
__device__ __forceinline__ u32 pkhf(float lo, float hi){
    u32 d; asm("cvt.rn.f16x2.f32 %0, %1, %2;" : "=r"(d) : "f"(hi), "f"(lo));
    return d;
}
__device__ __forceinline__ void cpasync16(u32 dst, const void* src){
    asm volatile("cp.async.cg.shared.global [%0], [%1], 16;" :: "r"(dst), "l"(src));
}
__device__ __forceinline__ u32 fbits(float x){ return __float_as_uint(x); }

// One warp per row: write tf32-rounded row + C1*|row~|^2
__global__ void prep_kernel(const float* __restrict__ P, const float* __restrict__ R)
{
    int warp = (blockIdx.x * blockDim.x + threadIdx.x) >> 5;
    int lane = threadIdx.x & 31;
    const float* src; float* dst; float* nrm;
    if (warp < 2 * Nq){
        src = P + (size_t)warp * Dq; dst = g_Pr + (size_t)warp * Dq; nrm = g_sqp + warp;
    } else {
        int row = warp - 2 * Nq;
        src = R + (size_t)row * Dq; dst = g_Rr + (size_t)row * Dq; nrm = g_sqr + row;
    }
    float2 v = ((const float2*)src)[lane];
    v.x = rtf(v.x); v.y = rtf(v.y);
    ((float2*)dst)[lane] = v;
    float s = v.x * v.x + v.y * v.y;
    #pragma unroll
    for (int o = 16; o; o >>= 1) s += __shfl_xor_sync(0xffffffffu, s, o);
    if (lane == 0) nrm[0] = s * C1F;
}

// Per 128-row chunk: write fp16 R^T tile [64 d][128 kk] (row stride 128 fp16)
__global__ void transpose_kernel(const float* __restrict__ Rsrc)
{
    __shared__ u32 st[64 * 68];
    const int chunk = blockIdx.x;               // b*64 + c, 0..127
    const int t = threadIdx.x;
    const float4* src = (const float4*)(Rsrc + (size_t)chunk * 128 * Dq);
    __half* bp = (__half*)st;
    #pragma unroll
    for (int it = 0; it < 8; it++){
        int idx = t + (it << 8);                // 0..2047
        int m = idx >> 4, j4 = idx & 15;        // m = kk row, j4*4 = d col
        float4 v = src[idx];
        bp[(4*j4 + 0) * 136 + m] = __float2half_rn(v.x);
        bp[(4*j4 + 1) * 136 + m] = __float2half_rn(v.y);
        bp[(4*j4 + 2) * 136 + m] = __float2half_rn(v.z);
        bp[(4*j4 + 3) * 136 + m] = __float2half_rn(v.w);
    }
    __syncthreads();
    u32* dst = g_Rt + (size_t)chunk * 4096;
    #pragma unroll
    for (int it = 0; it < 4; it++){
        int idx = t + (it << 8);                // 0..1023
        int j = idx >> 4, s = idx & 15;
        uint4 v = *(const uint4*)&st[j * 68 + s * 4];
        *(uint4*)&dst[j * 64 + s * 4] = v;
    }
}

__global__ void __launch_bounds__(256, 1) ms_kernel(float* __restrict__ out)
{
    extern __shared__ float sm[];
    float* Ps   = sm + OFF_P;
    float* Rs0  = sm + OFF_R;
    float* numb = sm + OFF_NUM;
    float* sqp  = sm + OFF_SQP;
    float* sqr0 = sm + OFF_SQR;
    float* denp = sm + OFF_DEN;
    u32*   Rt0  = (u32*)(sm + OFF_RT);

    const int t = threadIdx.x;
    const int w = t >> 5, l = t & 31;
    const int gid = l >> 2, tig = l & 3;
    const int b = blockIdx.y;
    const int n0 = blockIdx.x * TNr;
    const float* Pb = g_Pr + ((size_t)b * Nq + n0) * Dq;
    const float* Rb = g_Rr + (size_t)b * Mq * Dq;
    const u32*  Rtg = g_Rt + (size_t)b * 64 * 4096;
    const float* sqpg = g_sqp + b * Nq + n0;
    const float* sqrg = g_sqr + b * Mq;

    // Warp grid 4m x 2half: wm rows, half = GEMM1 n-slice = GEMM2 private k-half
    const int wm = (w & 3) * 32;
    const int half = w >> 2;
    const int wn1 = half * 64;

    // ---- Prologue: cp.async P + sqp + R chunk0 + Rt chunk0 + sqr0 ----
    {
        const float4* g4 = (const float4*)Pb;
        #pragma unroll
        for (int it = 0; it < 8; it++){
            int idx = t + (it << 8);
            int r = idx >> 4, c4 = idx & 15;
            cpasync16((u32)__cvta_generic_to_shared(&Ps[r * SR + c4 * 4]), g4 + idx);
        }
        const float4* r4 = (const float4*)Rb;
        #pragma unroll
        for (int it = 0; it < 8; it++){
            int idx = t + (it << 8);
            int r = idx >> 4, c4 = idx & 15;
            cpasync16((u32)__cvta_generic_to_shared(&Rs0[r * SR + c4 * 4]), r4 + idx);
        }
        #pragma unroll
        for (int it = 0; it < 4; it++){
            int idx = t + (it << 8);
            int j = idx >> 4, s = idx & 15;
            cpasync16((u32)__cvta_generic_to_shared(&Rt0[j * 68 + s * 4]),
                      Rtg + j * 64 + s * 4);
        }
        if (t < 32) cpasync16((u32)__cvta_generic_to_shared(&sqp[t * 4]), sqpg + t * 4);
        if (t >= 32 && t < 64)
            cpasync16((u32)__cvta_generic_to_shared(&sqr0[(t - 32) * 4]), sqrg + (t - 32) * 4);
        asm volatile("cp.async.commit_group;");
    }

    float nacc[2][8][4];
    float denacc[2][4];
    #pragma unroll
    for (int i = 0; i < 2; i++){
        #pragma unroll
        for (int j = 0; j < 8; j++)
            #pragma unroll
            for (int q = 0; q < 4; q++) nacc[i][j][q] = 0.f;
        #pragma unroll
        for (int q = 0; q < 4; q++) denacc[i][q] = 0.f;
    }
    const u32 ONE2 = 0x3C003C00u;   // f16x2 {1.0, 1.0}

    for (int i = 0; i < NCHUNK; i++){
        const int p = i & 1;
        float* Rs  = Rs0 + p * 128 * SR;
        float* sqr = sqr0 + p * 128;
        const u32* Rt = Rt0 + p * 64 * 68;

        asm volatile("cp.async.wait_group 0;" ::: "memory");
        __syncthreads();

        if (i + 1 < NCHUNK){
            float* Rn = Rs0 + (p ^ 1) * 128 * SR;
            u32* Rtn = Rt0 + (p ^ 1) * 64 * 68;
            const float4* g4 = (const float4*)(Rb + (size_t)(i + 1) * 128 * Dq);
            const u32* rtg = Rtg + (size_t)(i + 1) * 4096;
            #pragma unroll
            for (int it = 0; it < 8; it++){
                int idx = t + (it << 8);
                int r = idx >> 4, c4 = idx & 15;
                cpasync16((u32)__cvta_generic_to_shared(&Rn[r * SR + c4 * 4]), g4 + idx);
            }
            #pragma unroll
            for (int it = 0; it < 4; it++){
                int idx = t + (it << 8);
                int j = idx >> 4, s = idx & 15;
                cpasync16((u32)__cvta_generic_to_shared(&Rtn[j * 68 + s * 4]),
                          rtg + j * 64 + s * 4);
            }
            if (t < 32)
                cpasync16((u32)__cvta_generic_to_shared(&sqr0[(p ^ 1) * 128 + t * 4]),
                          sqrg + (size_t)(i + 1) * 128 + t * 4);
            asm volatile("cp.async.commit_group;");
        }

        // ---- GEMM1 (tf32): S = P . R^T  (warp tile 32 x 64) ----
        float sa[2][8][4];
        #pragma unroll
        for (int mt = 0; mt < 2; mt++)
            #pragma unroll
            for (int nt = 0; nt < 8; nt++)
                #pragma unroll
                for (int q = 0; q < 4; q++) sa[mt][nt][q] = 0.f;

        #pragma unroll
        for (int ks = 0; ks < 8; ks++){
            u32 a[2][4];
            #pragma unroll
            for (int mt = 0; mt < 2; mt++){
                const float* pa = &Ps[(wm + 16*mt + gid) * SR + ks*8 + tig];
                a[mt][0] = fbits(pa[0]);
                a[mt][1] = fbits(pa[8*SR]);
                a[mt][2] = fbits(pa[4]);
                a[mt][3] = fbits(pa[8*SR + 4]);
            }
            #pragma unroll
            for (int nt = 0; nt < 8; nt++){
                const float* pb = &Rs[(wn1 + 8*nt + gid) * SR + ks*8 + tig];
                u32 b0 = fbits(pb[0]), b1 = fbits(pb[4]);
                #pragma unroll
                for (int mt = 0; mt < 2; mt++)
                    mma_tf32(sa[mt][nt], a[mt][0], a[mt][1], a[mt][2], a[mt][3], b0, b1);
            }
        }

        // ---- Epilogue in registers: sa <- exp2(C2*S - |p|^2 - |r|^2) ----
        #pragma unroll
        for (int mt = 0; mt < 2; mt++){
            int r0 = wm + 16*mt + gid;
            float spa0 = sqp[r0];
            float spa1 = sqp[r0 + 8];
            #pragma unroll
            for (int nt = 0; nt < 8; nt++){
                int c0 = wn1 + 8*nt + 2*tig;
                float2 q = *(const float2*)&sqr[c0];
                sa[mt][nt][0] = ex2(fmaf(C2F, sa[mt][nt][0], -spa0 - q.x));
                sa[mt][nt][1] = ex2(fmaf(C2F, sa[mt][nt][1], -spa0 - q.y));
                sa[mt][nt][2] = ex2(fmaf(C2F, sa[mt][nt][2], -spa1 - q.x));
                sa[mt][nt][3] = ex2(fmaf(C2F, sa[mt][nt][3], -spa1 - q.y));
            }
        }

        // ---- GEMM2 (fp16 k16): num += K_regs . R ; den += K_regs . ones ----
        // C-frag (c0,c1 = cols 2tig,2tig+1; c2,c3 = rows +8) packs directly into
        // m16n8k16 A regs. B from fp16 R^T: 1 LDS.32 per reg, conflict-free.
        #pragma unroll
        for (int kt = 0; kt < 4; kt++){
            u32 a0[2], a1[2], a2[2], a3[2];
            #pragma unroll
            for (int mt = 0; mt < 2; mt++){
                a0[mt] = pkhf(sa[mt][2*kt][0],   sa[mt][2*kt][1]);
                a1[mt] = pkhf(sa[mt][2*kt][2],   sa[mt][2*kt][3]);
                a2[mt] = pkhf(sa[mt][2*kt+1][0], sa[mt][2*kt+1][1]);
                a3[mt] = pkhf(sa[mt][2*kt+1][2], sa[mt][2*kt+1][3]);
            }
            const int koff = (wn1 >> 1) + 8*kt + tig;   // u32 index along kk
            #pragma unroll
            for (int jt = 0; jt < 8; jt++){
                const u32* pb = &Rt[(8*jt + gid) * 68 + koff];
                u32 b0 = pb[0], b1 = pb[4];
                #pragma unroll
                for (int mt = 0; mt < 2; mt++)
                    mma_f16(nacc[mt][jt], a0[mt], a1[mt], a2[mt], a3[mt], b0, b1);
            }
            #pragma unroll
            for (int mt = 0; mt < 2; mt++)
                mma_f16(denacc[mt], a0[mt], a1[mt], a2[mt], a3[mt], ONE2, ONE2);
        }
    }

    // ---- Denominator partials (cols of ones-MMA identical) ----
    if (tig == 0){
        #pragma unroll
        for (int mt = 0; mt < 2; mt++){
            denp[half * 128 + wm + 16*mt + gid]     = denacc[mt][0];
            denp[half * 128 + wm + 16*mt + 8 + gid] = denacc[mt][2];
        }
    }

    // ---- Combine the two k-half numerator partials in SMEM ----
    __syncthreads();
    if (half == 0){
        #pragma unroll
        for (int mt = 0; mt < 2; mt++){
            int r0 = wm + 16*mt + gid;
            #pragma unroll
            for (int jt = 0; jt < 8; jt++){
                int c0 = 8*jt + 2*tig;
                *(float2*)&numb[r0 * SR + c0]       = make_float2(nacc[mt][jt][0], nacc[mt][jt][1]);
                *(float2*)&numb[(r0 + 8) * SR + c0] = make_float2(nacc[mt][jt][2], nacc[mt][jt][3]);
            }
        }
    }
    __syncthreads();
    if (half == 1){
        #pragma unroll
        for (int mt = 0; mt < 2; mt++){
            int r0 = wm + 16*mt + gid;
            #pragma unroll
            for (int jt = 0; jt < 8; jt++){
                int c0 = 8*jt + 2*tig;
                float2 u0 = *(const float2*)&numb[r0 * SR + c0];
                float2 u1 = *(const float2*)&numb[(r0 + 8) * SR + c0];
                u0.x += nacc[mt][jt][0]; u0.y += nacc[mt][jt][1];
                u1.x += nacc[mt][jt][2]; u1.y += nacc[mt][jt][3];
                *(float2*)&numb[r0 * SR + c0]       = u0;
                *(float2*)&numb[(r0 + 8) * SR + c0] = u1;
            }
        }
    }
    __syncthreads();

    // ---- Coalesced writeback: out = num / den ----
    float4* Ob = (float4*)(out + ((size_t)b * Nq + n0) * Dq);
    #pragma unroll
    for (int it = 0; it < 8; it++){
        int idx = t + (it << 8);
        int r = idx >> 4, c4 = idx & 15;
        float4 v = *(const float4*)&numb[r * SR + c4 * 4];
        float inv = rcpf(denp[r] + denp[128 + r]);
        v.x *= inv; v.y *= inv; v.z *= inv; v.w *= inv;
        Ob[idx] = v;
    }
}

extern "C" void kernel_launch(void* const* d_in, const int* in_sizes, int n_in,
                              void* d_out, int out_size)
{
    const float* points = (const float*)d_in[0];
    const float* refp   = (const float*)d_in[1];
    float* out          = (float*)d_out;

    {
        int warps = 2 * Nq + 2 * Mq;
        prep_kernel<<<warps / 8, 256>>>(points, refp);
    }
    transpose_kernel<<<128, 256>>>(refp);

    const int smem_bytes = SMEM_F * (int)sizeof(float);
    static int attr_set = 0;
    if (!attr_set){
        cudaFuncSetAttribute(ms_kernel,
                             cudaFuncAttributeMaxDynamicSharedMemorySize, smem_bytes);
        attr_set = 1;
    }
    dim3 grid(Nq / TNr, 2);
    ms_kernel<<<grid, 256, smem_bytes>>>(out);
}

// round 13
// speedup vs baseline: 1.8760x; 1.3185x over previous
#include <cuda_runtime.h>
#include <cuda_fp16.h>
#include <cstdint>

typedef unsigned int u32;

#define Nq 8192
#define Mq 8192
#define Dq 64
#define TNr 128
#define NCHUNK 64

#define SH 36    // fp16 tile row stride in u32: bank = 4*gid+tig = lane, conflict-free
#define SR 68    // fp32 staging row stride

#define C1F (1.0f/(128.0f*0.69314718055994531f))
#define C2F (2.0f*C1F)

// SMEM u32/float offsets
#define OFF_PH   0                          // 128 x SH u32 (fp16 P)
#define OFF_RH   (OFF_PH + 128*SH)          // 2 buffers x 128 x SH (fp16 R)
#define OFF_RT   (OFF_RH + 2*128*SH)        // 2 buffers x 64 x 68 u32 (fp16 R^T)
#define OFF_NUM  (OFF_RT + 2*64*68)         // 128 x SR fp32 num staging
#define OFF_SQP  (OFF_NUM + 128*SR)
#define OFF_SQR  (OFF_SQP + 128)            // 2 x 128
#define OFF_DEN  (OFF_SQR + 256)            // 2 x 128
#define SMEM_F   (OFF_DEN + 256)

// fp16-packed inputs + norms + transposed fp16 R
__device__ u32   g_Ph[2 * Nq * 32];
__device__ u32   g_Rh[2 * Mq * 32];
__device__ float g_sqp[2 * Nq];
__device__ float g_sqr[2 * Mq];
__device__ u32   g_Rt[2 * 64 * 4096];       // per chunk: 64 d-rows x 128 kk (fp16)

__device__ __forceinline__ void mma_f16(float c[4], u32 a0, u32 a1, u32 a2, u32 a3,
                                        u32 b0, u32 b1)
{
    asm volatile(
        "mma.sync.aligned.m16n8k16.row.col.f32.f16.f16.f32 "
        "{%0,%1,%2,%3}, {%4,%5,%6,%7}, {%8,%9}, {%0,%1,%2,%3};"
        : "+f"(c[0]), "+f"(c[1]), "+f"(c[2]), "+f"(c[3])
        : "r"(a0), "r"(a1), "r"(a2), "r"(a3), "r"(b0), "r"(b1));
}
__device__ __forceinline__ float ex2(float x){
    float r; asm("ex2.approx.ftz.f32 %0, %1;" : "=f"(r) : "f"(x)); return r;
}
__device__ __forceinline__ float rcpf(float x){
    float r; asm("rcp.approx.ftz.f32 %0, %1;" : "=f"(r) : "f"(x)); return r;
}
__device__ __forceinline__ u32 pkhf(float lo, float hi){
    u32 d; asm("cvt.rn.f16x2.f32 %0, %1, %2;" : "=r"(d) : "f"(hi), "f"(lo));
    return d;
}
__device__ __forceinline__ void cpasync16(u32 dst, const void* src){
    asm volatile("cp.async.cg.shared.global [%0], [%1], 16;" :: "r"(dst), "l"(src));
}

// One warp per row: pack fp16 row + C1*|row_h|^2 (norms from the ROUNDED values)
__global__ void prep_kernel(const float* __restrict__ P, const float* __restrict__ R)
{
    int warp = (blockIdx.x * blockDim.x + threadIdx.x) >> 5;
    int lane = threadIdx.x & 31;
    const float* src; u32* dst; float* nrm;
    if (warp < 2 * Nq){
        src = P + (size_t)warp * Dq; dst = g_Ph + (size_t)warp * 32; nrm = g_sqp + warp;
    } else {
        int row = warp - 2 * Nq;
        src = R + (size_t)row * Dq; dst = g_Rh + (size_t)row * 32; nrm = g_sqr + row;
    }
    float2 v = ((const float2*)src)[lane];
    float x = __half2float(__float2half_rn(v.x));
    float y = __half2float(__float2half_rn(v.y));
    dst[lane] = pkhf(x, y);
    float s = x * x + y * y;
    #pragma unroll
    for (int o = 16; o; o >>= 1) s += __shfl_xor_sync(0xffffffffu, s, o);
    if (lane == 0) nrm[0] = s * C1F;
}

// Per 128-row chunk: fp16 R^T tile [64 d][128 kk] (row stride 128 fp16 = 64 u32)
__global__ void transpose_kernel(const float* __restrict__ Rsrc)
{
    __shared__ u32 st[64 * 68];
    const int chunk = blockIdx.x;
    const int t = threadIdx.x;
    const float4* src = (const float4*)(Rsrc + (size_t)chunk * 128 * Dq);
    __half* bp = (__half*)st;
    #pragma unroll
    for (int it = 0; it < 8; it++){
        int idx = t + (it << 8);
        int m = idx >> 4, j4 = idx & 15;
        float4 v = src[idx];
        bp[(4*j4 + 0) * 136 + m] = __float2half_rn(v.x);
        bp[(4*j4 + 1) * 136 + m] = __float2half_rn(v.y);
        bp[(4*j4 + 2) * 136 + m] = __float2half_rn(v.z);
        bp[(4*j4 + 3) * 136 + m] = __float2half_rn(v.w);
    }
    __syncthreads();
    u32* dst = g_Rt + (size_t)chunk * 4096;
    #pragma unroll
    for (int it = 0; it < 4; it++){
        int idx = t + (it << 8);
        int j = idx >> 4, s = idx & 15;
        uint4 v = *(const uint4*)&st[j * 68 + s * 4];
        *(uint4*)&dst[j * 64 + s * 4] = v;
    }
}

__global__ void __launch_bounds__(256, 1) ms_kernel(float* __restrict__ out)
{
    extern __shared__ float sm[];
    u32*   Ph   = (u32*)sm + OFF_PH;
    u32*   Rh0  = (u32*)sm + OFF_RH;
    u32*   Rt0  = (u32*)sm + OFF_RT;
    float* numb = sm + OFF_NUM;
    float* sqp  = sm + OFF_SQP;
    float* sqr0 = sm + OFF_SQR;
    float* denp = sm + OFF_DEN;

    const int t = threadIdx.x;
    const int w = t >> 5, l = t & 31;
    const int gid = l >> 2, tig = l & 3;
    const int b = blockIdx.y;
    const int n0 = blockIdx.x * TNr;
    const u32* Phg = g_Ph + ((size_t)b * Nq + n0) * 32;
    const u32* Rhg = g_Rh + (size_t)b * Mq * 32;
    const u32* Rtg = g_Rt + (size_t)b * 64 * 4096;
    const float* sqpg = g_sqp + b * Nq + n0;
    const float* sqrg = g_sqr + b * Mq;

    const int wm = (w & 3) * 32;
    const int half = w >> 2;
    const int wn1 = half * 64;

    // ---- Prologue: cp.async P + R chunk0 + Rt chunk0 + norms ----
    {
        #pragma unroll
        for (int it = 0; it < 4; it++){
            int idx = t + (it << 8);            // 0..1023
            int r = idx >> 3, q = idx & 7;
            cpasync16((u32)__cvta_generic_to_shared(&Ph[r * SH + q * 4]), Phg + r * 32 + q * 4);
        }
        #pragma unroll
        for (int it = 0; it < 4; it++){
            int idx = t + (it << 8);
            int r = idx >> 3, q = idx & 7;
            cpasync16((u32)__cvta_generic_to_shared(&Rh0[r * SH + q * 4]), Rhg + r * 32 + q * 4);
        }
        #pragma unroll
        for (int it = 0; it < 4; it++){
            int idx = t + (it << 8);
            int j = idx >> 4, s = idx & 15;
            cpasync16((u32)__cvta_generic_to_shared(&Rt0[j * 68 + s * 4]), Rtg + j * 64 + s * 4);
        }
        if (t < 32) cpasync16((u32)__cvta_generic_to_shared(&sqp[t * 4]), sqpg + t * 4);
        if (t >= 32 && t < 64)
            cpasync16((u32)__cvta_generic_to_shared(&sqr0[(t - 32) * 4]), sqrg + (t - 32) * 4);
        asm volatile("cp.async.commit_group;");
    }

    float nacc[2][8][4];
    float denacc[2][4];
    #pragma unroll
    for (int i = 0; i < 2; i++){
        #pragma unroll
        for (int j = 0; j < 8; j++)
            #pragma unroll
            for (int q = 0; q < 4; q++) nacc[i][j][q] = 0.f;
        #pragma unroll
        for (int q = 0; q < 4; q++) denacc[i][q] = 0.f;
    }
    const u32 ONE2 = 0x3C003C00u;   // f16x2 {1,1}

    for (int i = 0; i < NCHUNK; i++){
        const int p = i & 1;
        const u32* Rh = Rh0 + p * 128 * SH;
        const u32* Rt = Rt0 + p * 64 * 68;
        float* sqr = sqr0 + p * 128;

        asm volatile("cp.async.wait_group 0;" ::: "memory");
        __syncthreads();

        if (i + 1 < NCHUNK){
            u32* Rn  = Rh0 + (p ^ 1) * 128 * SH;
            u32* Rtn = Rt0 + (p ^ 1) * 64 * 68;
            const u32* rhg = Rhg + (size_t)(i + 1) * 128 * 32;
            const u32* rtg = Rtg + (size_t)(i + 1) * 4096;
            #pragma unroll
            for (int it = 0; it < 4; it++){
                int idx = t + (it << 8);
                int r = idx >> 3, q = idx & 7;
                cpasync16((u32)__cvta_generic_to_shared(&Rn[r * SH + q * 4]), rhg + r * 32 + q * 4);
            }
            #pragma unroll
            for (int it = 0; it < 4; it++){
                int idx = t + (it << 8);
                int j = idx >> 4, s = idx & 15;
                cpasync16((u32)__cvta_generic_to_shared(&Rtn[j * 68 + s * 4]), rtg + j * 64 + s * 4);
            }
            if (t < 32)
                cpasync16((u32)__cvta_generic_to_shared(&sqr0[(p ^ 1) * 128 + t * 4]),
                          sqrg + (size_t)(i + 1) * 128 + t * 4);
            asm volatile("cp.async.commit_group;");
        }

        // ---- GEMM1 (fp16 k16): S = P . R^T  (warp tile 32 x 64) ----
        float sa[2][8][4];
        #pragma unroll
        for (int mt = 0; mt < 2; mt++)
            #pragma unroll
            for (int nt = 0; nt < 8; nt++)
                #pragma unroll
                for (int q = 0; q < 4; q++) sa[mt][nt][q] = 0.f;

        #pragma unroll
        for (int ks = 0; ks < 4; ks++){
            u32 a[2][4];
            #pragma unroll
            for (int mt = 0; mt < 2; mt++){
                const u32* pa = &Ph[(wm + 16*mt + gid) * SH + ks*8 + tig];
                a[mt][0] = pa[0];
                a[mt][1] = pa[8*SH];
                a[mt][2] = pa[4];
                a[mt][3] = pa[8*SH + 4];
            }
            #pragma unroll
            for (int nt = 0; nt < 8; nt++){
                const u32* pb = &Rh[(wn1 + 8*nt + gid) * SH + ks*8 + tig];
                u32 b0 = pb[0], b1 = pb[4];
                #pragma unroll
                for (int mt = 0; mt < 2; mt++)
                    mma_f16(sa[mt][nt], a[mt][0], a[mt][1], a[mt][2], a[mt][3], b0, b1);
            }
        }

        // ---- Epilogue in registers: sa <- exp2(C2*S - |p|^2 - |r|^2) ----
        #pragma unroll
        for (int mt = 0; mt < 2; mt++){
            int r0 = wm + 16*mt + gid;
            float spa0 = sqp[r0];
            float spa1 = sqp[r0 + 8];
            #pragma unroll
            for (int nt = 0; nt < 8; nt++){
                int c0 = wn1 + 8*nt + 2*tig;
                float2 q = *(const float2*)&sqr[c0];
                sa[mt][nt][0] = ex2(fmaf(C2F, sa[mt][nt][0], -spa0 - q.x));
                sa[mt][nt][1] = ex2(fmaf(C2F, sa[mt][nt][1], -spa0 - q.y));
                sa[mt][nt][2] = ex2(fmaf(C2F, sa[mt][nt][2], -spa1 - q.x));
                sa[mt][nt][3] = ex2(fmaf(C2F, sa[mt][nt][3], -spa1 - q.y));
            }
        }

        // ---- GEMM2 (fp16 k16): num += K_regs . R ; den += K_regs . ones ----
        #pragma unroll
        for (int kt = 0; kt < 4; kt++){
            u32 a0[2], a1[2], a2[2], a3[2];
            #pragma unroll
            for (int mt = 0; mt < 2; mt++){
                a0[mt] = pkhf(sa[mt][2*kt][0],   sa[mt][2*kt][1]);
                a1[mt] = pkhf(sa[mt][2*kt][2],   sa[mt][2*kt][3]);
                a2[mt] = pkhf(sa[mt][2*kt+1][0], sa[mt][2*kt+1][1]);
                a3[mt] = pkhf(sa[mt][2*kt+1][2], sa[mt][2*kt+1][3]);
            }
            const int koff = (wn1 >> 1) + 8*kt + tig;
            #pragma unroll
            for (int jt = 0; jt < 8; jt++){
                const u32* pb = &Rt[(8*jt + gid) * 68 + koff];
                u32 b0 = pb[0], b1 = pb[4];
                #pragma unroll
                for (int mt = 0; mt < 2; mt++)
                    mma_f16(nacc[mt][jt], a0[mt], a1[mt], a2[mt], a3[mt], b0, b1);
            }
            #pragma unroll
            for (int mt = 0; mt < 2; mt++)
                mma_f16(denacc[mt], a0[mt], a1[mt], a2[mt], a3[mt], ONE2, ONE2);
        }
    }

    // ---- Denominator partials ----
    if (tig == 0){
        #pragma unroll
        for (int mt = 0; mt < 2; mt++){
            denp[half * 128 + wm + 16*mt + gid]     = denacc[mt][0];
            denp[half * 128 + wm + 16*mt + 8 + gid] = denacc[mt][2];
        }
    }

    // ---- Combine the two k-half numerator partials in SMEM ----
    __syncthreads();
    if (half == 0){
        #pragma unroll
        for (int mt = 0; mt < 2; mt++){
            int r0 = wm + 16*mt + gid;
            #pragma unroll
            for (int jt = 0; jt < 8; jt++){
                int c0 = 8*jt + 2*tig;
                *(float2*)&numb[r0 * SR + c0]       = make_float2(nacc[mt][jt][0], nacc[mt][jt][1]);
                *(float2*)&numb[(r0 + 8) * SR + c0] = make_float2(nacc[mt][jt][2], nacc[mt][jt][3]);
            }
        }
    }
    __syncthreads();
    if (half == 1){
        #pragma unroll
        for (int mt = 0; mt < 2; mt++){
            int r0 = wm + 16*mt + gid;
            #pragma unroll
            for (int jt = 0; jt < 8; jt++){
                int c0 = 8*jt + 2*tig;
                float2 u0 = *(const float2*)&numb[r0 * SR + c0];
                float2 u1 = *(const float2*)&numb[(r0 + 8) * SR + c0];
                u0.x += nacc[mt][jt][0]; u0.y += nacc[mt][jt][1];
                u1.x += nacc[mt][jt][2]; u1.y += nacc[mt][jt][3];
                *(float2*)&numb[r0 * SR + c0]       = u0;
                *(float2*)&numb[(r0 + 8) * SR + c0] = u1;
            }
        }
    }
    __syncthreads();

    // ---- Coalesced writeback: out = num / den ----
    float4* Ob = (float4*)(out + ((size_t)b * Nq + n0) * Dq);
    #pragma unroll
    for (int it = 0; it < 8; it++){
        int idx = t + (it << 8);
        int r = idx >> 4, c4 = idx & 15;
        float4 v = *(const float4*)&numb[r * SR + c4 * 4];
        float inv = rcpf(denp[r] + denp[128 + r]);
        v.x *= inv; v.y *= inv; v.z *= inv; v.w *= inv;
        Ob[idx] = v;
    }
}

extern "C" void kernel_launch(void* const* d_in, const int* in_sizes, int n_in,
                              void* d_out, int out_size)
{
    const float* points = (const float*)d_in[0];
    const float* refp   = (const float*)d_in[1];
    float* out          = (float*)d_out;

    {
        int warps = 2 * Nq + 2 * Mq;
        prep_kernel<<<warps / 8, 256>>>(points, refp);
    }
    transpose_kernel<<<128, 256>>>(refp);

    const int smem_bytes = SMEM_F * (int)sizeof(float);
    static int attr_set = 0;
    if (!attr_set){
        cudaFuncSetAttribute(ms_kernel,
                             cudaFuncAttributeMaxDynamicSharedMemorySize, smem_bytes);
        attr_set = 1;
    }
    dim3 grid(Nq / TNr, 2);
    ms_kernel<<<grid, 256, smem_bytes>>>(out);
}

// round 14
// speedup vs baseline: 1.9570x; 1.0432x over previous
#include <cuda_runtime.h>
#include <cuda_fp16.h>
#include <cstdint>

typedef unsigned int u32;

#define Nq 8192
#define Mq 8192
#define Dq 64
#define TNr 128
#define NCHUNK 64

#define SH 36    // fp16 tile row stride in u32: conflict-free frag patterns
#define SR 68    // fp32 staging row stride

#define C1F (1.0f/(128.0f*0.69314718055994531f))
#define C2F (2.0f*C1F)

// SMEM u32 offsets
#define OFF_PH   0                          // 128 x SH (fp16 P)
#define OFF_RH   (OFF_PH + 128*SH)          // 4 buffers x 128 x SH (fp16 R)
#define OFF_RT   (OFF_RH + 4*128*SH)        // 4 buffers x 64 x 68 (fp16 R^T)
#define OFF_NUM  (OFF_RT + 4*64*68)         // 128 x SR fp32 num staging
#define OFF_SQP  (OFF_NUM + 128*SR)
#define OFF_SQR  (OFF_SQP + 128)            // 4 x 128
#define OFF_DEN  (OFF_SQR + 512)            // 2 x 128
#define SMEM_F   (OFF_DEN + 256)

__device__ u32   g_Ph[2 * Nq * 32];
__device__ u32   g_Rh[2 * Mq * 32];
__device__ float g_sqp[2 * Nq];
__device__ float g_sqr[2 * Mq];
__device__ u32   g_Rt[2 * 64 * 4096];

__device__ __forceinline__ void mma_f16(float c[4], u32 a0, u32 a1, u32 a2, u32 a3,
                                        u32 b0, u32 b1)
{
    asm volatile(
        "mma.sync.aligned.m16n8k16.row.col.f32.f16.f16.f32 "
        "{%0,%1,%2,%3}, {%4,%5,%6,%7}, {%8,%9}, {%0,%1,%2,%3};"
        : "+f"(c[0]), "+f"(c[1]), "+f"(c[2]), "+f"(c[3])
        : "r"(a0), "r"(a1), "r"(a2), "r"(a3), "r"(b0), "r"(b1));
}
__device__ __forceinline__ float ex2(float x){
    float r; asm("ex2.approx.ftz.f32 %0, %1;" : "=f"(r) : "f"(x)); return r;
}
__device__ __forceinline__ float rcpf(float x){
    float r; asm("rcp.approx.ftz.f32 %0, %1;" : "=f"(r) : "f"(x)); return r;
}
__device__ __forceinline__ u32 pkhf(float lo, float hi){
    u32 d; asm("cvt.rn.f16x2.f32 %0, %1, %2;" : "=r"(d) : "f"(hi), "f"(lo));
    return d;
}
__device__ __forceinline__ void cpasync16(u32 dst, const void* src){
    asm volatile("cp.async.cg.shared.global [%0], [%1], 16;" :: "r"(dst), "l"(src));
}

__global__ void prep_kernel(const float* __restrict__ P, const float* __restrict__ R)
{
    int warp = (blockIdx.x * blockDim.x + threadIdx.x) >> 5;
    int lane = threadIdx.x & 31;
    const float* src; u32* dst; float* nrm;
    if (warp < 2 * Nq){
        src = P + (size_t)warp * Dq; dst = g_Ph + (size_t)warp * 32; nrm = g_sqp + warp;
    } else {
        int row = warp - 2 * Nq;
        src = R + (size_t)row * Dq; dst = g_Rh + (size_t)row * 32; nrm = g_sqr + row;
    }
    float2 v = ((const float2*)src)[lane];
    float x = __half2float(__float2half_rn(v.x));
    float y = __half2float(__float2half_rn(v.y));
    dst[lane] = pkhf(x, y);
    float s = x * x + y * y;
    #pragma unroll
    for (int o = 16; o; o >>= 1) s += __shfl_xor_sync(0xffffffffu, s, o);
    if (lane == 0) nrm[0] = s * C1F;
}

__global__ void transpose_kernel(const float* __restrict__ Rsrc)
{
    __shared__ u32 st[64 * 68];
    const int chunk = blockIdx.x;
    const int t = threadIdx.x;
    const float4* src = (const float4*)(Rsrc + (size_t)chunk * 128 * Dq);
    __half* bp = (__half*)st;
    #pragma unroll
    for (int it = 0; it < 8; it++){
        int idx = t + (it << 8);
        int m = idx >> 4, j4 = idx & 15;
        float4 v = src[idx];
        bp[(4*j4 + 0) * 136 + m] = __float2half_rn(v.x);
        bp[(4*j4 + 1) * 136 + m] = __float2half_rn(v.y);
        bp[(4*j4 + 2) * 136 + m] = __float2half_rn(v.z);
        bp[(4*j4 + 3) * 136 + m] = __float2half_rn(v.w);
    }
    __syncthreads();
    u32* dst = g_Rt + (size_t)chunk * 4096;
    #pragma unroll
    for (int it = 0; it < 4; it++){
        int idx = t + (it << 8);
        int j = idx >> 4, s = idx & 15;
        uint4 v = *(const uint4*)&st[j * 68 + s * 4];
        *(uint4*)&dst[j * 64 + s * 4] = v;
    }
}

// Issue cp.async for one chunk's Rh + Rt + sqr into given slots
__device__ __forceinline__ void load_chunk(u32* RhD, u32* RtD, float* sqD,
                                           const u32* rhg, const u32* rtg,
                                           const float* sqg, int t)
{
    #pragma unroll
    for (int it = 0; it < 4; it++){
        int idx = t + (it << 8);
        int r = idx >> 3, q = idx & 7;
        cpasync16((u32)__cvta_generic_to_shared(&RhD[r * SH + q * 4]), rhg + r * 32 + q * 4);
    }
    #pragma unroll
    for (int it = 0; it < 4; it++){
        int idx = t + (it << 8);
        int j = idx >> 4, s2 = idx & 15;
        cpasync16((u32)__cvta_generic_to_shared(&RtD[j * 68 + s2 * 4]), rtg + j * 64 + s2 * 4);
    }
    if (t < 32) cpasync16((u32)__cvta_generic_to_shared(&sqD[t * 4]), sqg + t * 4);
}

__global__ void __launch_bounds__(256, 1) ms_kernel(float* __restrict__ out)
{
    extern __shared__ float sm[];
    u32*   Ph   = (u32*)sm + OFF_PH;
    u32*   Rh0  = (u32*)sm + OFF_RH;
    u32*   Rt0  = (u32*)sm + OFF_RT;
    float* numb = sm + OFF_NUM;
    float* sqp  = sm + OFF_SQP;
    float* sqr0 = sm + OFF_SQR;
    float* denp = sm + OFF_DEN;

    const int t = threadIdx.x;
    const int w = t >> 5, l = t & 31;
    const int gid = l >> 2, tig = l & 3;
    const int b = blockIdx.y;
    const int n0 = blockIdx.x * TNr;
    const u32* Phg = g_Ph + ((size_t)b * Nq + n0) * 32;
    const u32* Rhg = g_Rh + (size_t)b * Mq * 32;
    const u32* Rtg = g_Rt + (size_t)b * 64 * 4096;
    const float* sqpg = g_sqp + b * Nq + n0;
    const float* sqrg = g_sqr + b * Mq;

    const int wm = (w & 3) * 32;
    const int half = w >> 2;
    const int wn1 = half * 64;

    // ---- Prologue: group0 = Ph + sqp + chunk0 ; group1 = chunk1 ----
    {
        #pragma unroll
        for (int it = 0; it < 4; it++){
            int idx = t + (it << 8);
            int r = idx >> 3, q = idx & 7;
            cpasync16((u32)__cvta_generic_to_shared(&Ph[r * SH + q * 4]), Phg + r * 32 + q * 4);
        }
        if (t < 32) cpasync16((u32)__cvta_generic_to_shared(&sqp[t * 4]), sqpg + t * 4);
        load_chunk(Rh0, Rt0, sqr0, Rhg, Rtg, sqrg, t);
        asm volatile("cp.async.commit_group;");
        load_chunk(Rh0 + 128*SH, Rt0 + 64*68, sqr0 + 128,
                   Rhg + 128*32, Rtg + 4096, sqrg + 128, t);
        asm volatile("cp.async.commit_group;");
    }

    float nacc[2][8][4];
    float denacc[2][4];
    #pragma unroll
    for (int i = 0; i < 2; i++){
        #pragma unroll
        for (int j = 0; j < 8; j++)
            #pragma unroll
            for (int q = 0; q < 4; q++) nacc[i][j][q] = 0.f;
        #pragma unroll
        for (int q = 0; q < 4; q++) denacc[i][q] = 0.f;
    }
    const u32 ONE2 = 0x3C003C00u;
    u32 kp[2][4][4];   // packed K fragment of chunk i-1 (loop-carried)

    for (int i = 0; i < NCHUNK; i++){
        const int s = i & 3;
        const u32* Rh = Rh0 + s * 128 * SH;
        const float* sqr = sqr0 + s * 128;

        asm volatile("cp.async.wait_group 1;" ::: "memory");
        __syncthreads();

        // ---- GEMM1 (fp16): S = P . R^T  (warp tile 32 x 64) ----
        float sa[2][8][4];
        #pragma unroll
        for (int mt = 0; mt < 2; mt++)
            #pragma unroll
            for (int nt = 0; nt < 8; nt++)
                #pragma unroll
                for (int q = 0; q < 4; q++) sa[mt][nt][q] = 0.f;

        #pragma unroll
        for (int ks = 0; ks < 4; ks++){
            u32 a[2][4];
            #pragma unroll
            for (int mt = 0; mt < 2; mt++){
                const u32* pa = &Ph[(wm + 16*mt + gid) * SH + ks*8 + tig];
                a[mt][0] = pa[0];
                a[mt][1] = pa[8*SH];
                a[mt][2] = pa[4];
                a[mt][3] = pa[8*SH + 4];
            }
            #pragma unroll
            for (int nt = 0; nt < 8; nt++){
                const u32* pb = &Rh[(wn1 + 8*nt + gid) * SH + ks*8 + tig];
                u32 b0 = pb[0], b1 = pb[4];
                #pragma unroll
                for (int mt = 0; mt < 2; mt++)
                    mma_f16(sa[mt][nt], a[mt][0], a[mt][1], a[mt][2], a[mt][3], b0, b1);
            }
        }

        // ---- Prefetch chunk i+2 (slot free: its readers ran in iter i-2) ----
        if (i + 2 < NCHUNK){
            int s2 = (i + 2) & 3;
            load_chunk(Rh0 + s2 * 128 * SH, Rt0 + s2 * 64 * 68, sqr0 + s2 * 128,
                       Rhg + (size_t)(i + 2) * 128 * 32,
                       Rtg + (size_t)(i + 2) * 4096,
                       sqrg + (size_t)(i + 2) * 128, t);
        }
        asm volatile("cp.async.commit_group;");

        // ---- Fused: epilogue(i) [MUFU] interleaved with GEMM2(i-1) [tensor] ----
        const u32* Rtp = Rt0 + ((i + 3) & 3) * (64 * 68);
        u32 kc[2][4][4];
        #pragma unroll
        for (int kt = 0; kt < 4; kt++){
            #pragma unroll
            for (int mt = 0; mt < 2; mt++){
                int r0 = wm + 16*mt + gid;
                float spa0 = sqp[r0];
                float spa1 = sqp[r0 + 8];
                #pragma unroll
                for (int h = 0; h < 2; h++){
                    int nt = 2*kt + h;
                    int c0 = wn1 + 8*nt + 2*tig;
                    float2 q = *(const float2*)&sqr[c0];
                    float e0 = ex2(fmaf(C2F, sa[mt][nt][0], -spa0 - q.x));
                    float e1 = ex2(fmaf(C2F, sa[mt][nt][1], -spa0 - q.y));
                    float e2 = ex2(fmaf(C2F, sa[mt][nt][2], -spa1 - q.x));
                    float e3 = ex2(fmaf(C2F, sa[mt][nt][3], -spa1 - q.y));
                    kc[mt][kt][2*h + 0] = pkhf(e0, e1);
                    kc[mt][kt][2*h + 1] = pkhf(e2, e3);
                }
            }
            if (i > 0){
                const int koff = (wn1 >> 1) + 8*kt + tig;
                #pragma unroll
                for (int jt = 0; jt < 8; jt++){
                    const u32* pb = &Rtp[(8*jt + gid) * 68 + koff];
                    u32 b0 = pb[0], b1 = pb[4];
                    #pragma unroll
                    for (int mt = 0; mt < 2; mt++)
                        mma_f16(nacc[mt][jt], kp[mt][kt][0], kp[mt][kt][1],
                                kp[mt][kt][2], kp[mt][kt][3], b0, b1);
                }
                #pragma unroll
                for (int mt = 0; mt < 2; mt++)
                    mma_f16(denacc[mt], kp[mt][kt][0], kp[mt][kt][1],
                            kp[mt][kt][2], kp[mt][kt][3], ONE2, ONE2);
            }
        }
        // carry K(i) into next iteration
        #pragma unroll
        for (int mt = 0; mt < 2; mt++)
            #pragma unroll
            for (int kt = 0; kt < 4; kt++)
                #pragma unroll
                for (int q = 0; q < 4; q++)
                    kp[mt][kt][q] = kc[mt][kt][q];
    }

    // ---- Drain: GEMM2 for the last chunk ----
    {
        const u32* Rtp = Rt0 + ((NCHUNK - 1) & 3) * (64 * 68);
        #pragma unroll
        for (int kt = 0; kt < 4; kt++){
            const int koff = (wn1 >> 1) + 8*kt + tig;
            #pragma unroll
            for (int jt = 0; jt < 8; jt++){
                const u32* pb = &Rtp[(8*jt + gid) * 68 + koff];
                u32 b0 = pb[0], b1 = pb[4];
                #pragma unroll
                for (int mt = 0; mt < 2; mt++)
                    mma_f16(nacc[mt][jt], kp[mt][kt][0], kp[mt][kt][1],
                            kp[mt][kt][2], kp[mt][kt][3], b0, b1);
            }
            #pragma unroll
            for (int mt = 0; mt < 2; mt++)
                mma_f16(denacc[mt], kp[mt][kt][0], kp[mt][kt][1],
                        kp[mt][kt][2], kp[mt][kt][3], ONE2, ONE2);
        }
    }

    // ---- Denominator partials ----
    if (tig == 0){
        #pragma unroll
        for (int mt = 0; mt < 2; mt++){
            denp[half * 128 + wm + 16*mt + gid]     = denacc[mt][0];
            denp[half * 128 + wm + 16*mt + 8 + gid] = denacc[mt][2];
        }
    }

    // ---- Combine the two k-half numerator partials in SMEM ----
    __syncthreads();
    if (half == 0){
        #pragma unroll
        for (int mt = 0; mt < 2; mt++){
            int r0 = wm + 16*mt + gid;
            #pragma unroll
            for (int jt = 0; jt < 8; jt++){
                int c0 = 8*jt + 2*tig;
                *(float2*)&numb[r0 * SR + c0]       = make_float2(nacc[mt][jt][0], nacc[mt][jt][1]);
                *(float2*)&numb[(r0 + 8) * SR + c0] = make_float2(nacc[mt][jt][2], nacc[mt][jt][3]);
            }
        }
    }
    __syncthreads();
    if (half == 1){
        #pragma unroll
        for (int mt = 0; mt < 2; mt++){
            int r0 = wm + 16*mt + gid;
            #pragma unroll
            for (int jt = 0; jt < 8; jt++){
                int c0 = 8*jt + 2*tig;
                float2 u0 = *(const float2*)&numb[r0 * SR + c0];
                float2 u1 = *(const float2*)&numb[(r0 + 8) * SR + c0];
                u0.x += nacc[mt][jt][0]; u0.y += nacc[mt][jt][1];
                u1.x += nacc[mt][jt][2]; u1.y += nacc[mt][jt][3];
                *(float2*)&numb[r0 * SR + c0]       = u0;
                *(float2*)&numb[(r0 + 8) * SR + c0] = u1;
            }
        }
    }
    __syncthreads();

    // ---- Coalesced writeback: out = num / den ----
    float4* Ob = (float4*)(out + ((size_t)b * Nq + n0) * Dq);
    #pragma unroll
    for (int it = 0; it < 8; it++){
        int idx = t + (it << 8);
        int r = idx >> 4, c4 = idx & 15;
        float4 v = *(const float4*)&numb[r * SR + c4 * 4];
        float inv = rcpf(denp[r] + denp[128 + r]);
        v.x *= inv; v.y *= inv; v.z *= inv; v.w *= inv;
        Ob[idx] = v;
    }
}

extern "C" void kernel_launch(void* const* d_in, const int* in_sizes, int n_in,
                              void* d_out, int out_size)
{
    const float* points = (const float*)d_in[0];
    const float* refp   = (const float*)d_in[1];
    float* out          = (float*)d_out;

    {
        int warps = 2 * Nq + 2 * Mq;
        prep_kernel<<<warps / 8, 256>>>(points, refp);
    }
    transpose_kernel<<<128, 256>>>(refp);

    const int smem_bytes = SMEM_F * (int)sizeof(float);
    static int attr_set = 0;
    if (!attr_set){
        cudaFuncSetAttribute(ms_kernel,
                             cudaFuncAttributeMaxDynamicSharedMemorySize, smem_bytes);
        attr_set = 1;
    }
    dim3 grid(Nq / TNr, 2);
    ms_kernel<<<grid, 256, smem_bytes>>>(out);
}